// round 13
// baseline (speedup 1.0000x reference)
#include <cuda_runtime.h>

#define BATCH 256
#define SEQ   2048
#define EMBD  16
#define HIDD  32
#define GATE  128

typedef unsigned long long u64;
typedef unsigned int       u32;

// 256 MB scratch: gate-packed input projection, float4(i,f,g,o) per (token, hid)
__device__ float4 g_zx[(size_t)BATCH * SEQ * HIDD];

__device__ __forceinline__ u64 pack2(float lo, float hi){
    u64 r; asm("mov.b64 %0, {%1,%2};" : "=l"(r) : "f"(lo), "f"(hi)); return r;
}
__device__ __forceinline__ void unpack2(u64 v, float& lo, float& hi){
    asm("mov.b64 {%0,%1}, %2;" : "=f"(lo), "=f"(hi) : "l"(v));
}
__device__ __forceinline__ u64 ffma2(u64 a, u64 b, u64 c){
    u64 d; asm("fma.rn.f32x2 %0, %1, %2, %3;" : "=l"(d) : "l"(a), "l"(b), "l"(c)); return d;
}
__device__ __forceinline__ float tanha(float x){
    float y; asm("tanh.approx.f32 %0, %1;" : "=f"(y) : "f"(x)); return y;
}
// sigmoid(z) = 0.5 + 0.5*tanh(z/2)
__device__ __forceinline__ float sigt(float z){
    return fmaf(0.5f, tanha(0.5f * z), 0.5f);
}
__device__ __forceinline__ u32 smem_u32(const void* p){
    u32 a;
    asm("{ .reg .u64 t; cvta.to.shared.u64 t, %1; cvt.u32.u64 %0, t; }"
        : "=r"(a) : "l"(p));
    return a;
}
__device__ __forceinline__ void sts32(u32 addr, float v){
    asm volatile("st.shared.f32 [%0], %1;" :: "r"(addr), "f"(v) : "memory");
}
__device__ __forceinline__ float4 lds128(u32 addr){
    float4 v;
    asm volatile("ld.shared.v4.f32 {%0,%1,%2,%3}, [%4];"
        : "=f"(v.x), "=f"(v.y), "=f"(v.z), "=f"(v.w) : "r"(addr));
    return v;
}

// ─────────────── Phase 1: zx = emb[tok]@Wk + b  (proven, ~85us) ─────────────
__global__ __launch_bounds__(256) void proj_kernel(
    const int*   __restrict__ tokens,
    const float* __restrict__ emb,
    const float* __restrict__ Wk,
    const float* __restrict__ bias)
{
    const int j    = threadIdx.x & 31;
    const int warp = (blockIdx.x << 3) + (threadIdx.x >> 5);
    const int base = warp << 8;

    u64 wk_if[EMBD], wk_go[EMBD];
    #pragma unroll
    for (int e = 0; e < EMBD; e++){
        wk_if[e] = pack2(Wk[e*GATE + j],      Wk[e*GATE + j + 32]);
        wk_go[e] = pack2(Wk[e*GATE + j + 64], Wk[e*GATE + j + 96]);
    }
    const u64 b_if = pack2(bias[j],      bias[j + 32]);
    const u64 b_go = pack2(bias[j + 64], bias[j + 96]);

    for (int s = 0; s < 256; s += 2){
        const int tflat = base + s + (j >> 4);
        const int tok   = tokens[tflat];
        const float xv  = emb[tok * EMBD + (j & 15)];

        u64 aI = b_if, aG = b_go;
        u64 cI = b_if, cG = b_go;
        #pragma unroll
        for (int e = 0; e < EMBD; e++){
            float xa = __shfl_sync(0xffffffffu, xv, e);
            float xb = __shfl_sync(0xffffffffu, xv, 16 + e);
            u64 xa2 = pack2(xa, xa);
            u64 xb2 = pack2(xb, xb);
            aI = ffma2(xa2, wk_if[e], aI);
            aG = ffma2(xa2, wk_go[e], aG);
            cI = ffma2(xb2, wk_if[e], cI);
            cG = ffma2(xb2, wk_go[e], cG);
        }
        float4 zA, zB;
        unpack2(aI, zA.x, zA.y); unpack2(aG, zA.z, zA.w);
        unpack2(cI, zB.x, zB.y); unpack2(cG, zB.z, zB.w);
        g_zx[(size_t)(base + s)     * HIDD + j] = zA;
        g_zx[(size_t)(base + s + 1) * HIDD + j] = zB;
    }
}

// ─────────────── Phase 2: recurrence, 2 interleaved sequences per warp ──────
// R11 structure (whole sequence per warp, spill-proof named rings, barrier-
// free private smem h handoff) but each warp owns TWO independent sequences,
// their bodies merged into one branch-free basic block. R11/R12 showed the
// step is latency-bound (~150 cyc slack at ~300 issue slots): the second
// sequence's FFMAs fill the first's dependency stalls. Wr weight registers
// (128) are shared by both sequences, so marginal cost is rings/state only.
#define CHAIN4(acc, hh, ww, base)                       \
    acc = fmaf((hh).x, ww[(base)  ], acc);              \
    acc = fmaf((hh).y, ww[(base)+1], acc);              \
    acc = fmaf((hh).z, ww[(base)+2], acc);              \
    acc = fmaf((hh).w, ww[(base)+3], acc);

#define LSTM_BODY(HB, HA, ZP, TP, OP, Z, TK, H, C, tt)                  \
{                                                                       \
    const float4 z4  = Z;                                               \
    const int    tok = TK;                                              \
    const int    pidx = min((tt) + 2, SEQ - 1);                         \
    Z  = ZP[(size_t)pidx * HIDD];      /* refill slot for step tt+2 */  \
    TK = TP[pidx];                                                      \
    const float4 h0 = lds128((HB) +   0u);                              \
    const float4 h1 = lds128((HB) +  16u);                              \
    const float4 h2 = lds128((HB) +  32u);                              \
    const float4 h3 = lds128((HB) +  48u);                              \
    const float4 h4 = lds128((HB) +  64u);                              \
    const float4 h5 = lds128((HB) +  80u);                              \
    const float4 h6 = lds128((HB) +  96u);                              \
    const float4 h7 = lds128((HB) + 112u);                              \
    float i0 = z4.x, f0 = z4.y, g0 = z4.z;                              \
    float i1 = 0.f,  f1 = 0.f,  g1 = 0.f;                               \
    CHAIN4(i0, h0, wi, 0)  CHAIN4(f0, h0, wf, 0)  CHAIN4(g0, h0, wg, 0) \
    CHAIN4(i0, h1, wi, 4)  CHAIN4(f0, h1, wf, 4)  CHAIN4(g0, h1, wg, 4) \
    CHAIN4(i0, h2, wi, 8)  CHAIN4(f0, h2, wf, 8)  CHAIN4(g0, h2, wg, 8) \
    CHAIN4(i0, h3, wi,12)  CHAIN4(f0, h3, wf,12)  CHAIN4(g0, h3, wg,12) \
    CHAIN4(i1, h4, wi,16)  CHAIN4(f1, h4, wf,16)  CHAIN4(g1, h4, wg,16) \
    CHAIN4(i1, h5, wi,20)  CHAIN4(f1, h5, wf,20)  CHAIN4(g1, h5, wg,20) \
    CHAIN4(i1, h6, wi,24)  CHAIN4(f1, h6, wf,24)  CHAIN4(g1, h6, wg,24) \
    CHAIN4(i1, h7, wi,28)  CHAIN4(f1, h7, wf,28)  CHAIN4(g1, h7, wg,28) \
    const float gi = sigt(i0 + i1);                                     \
    const float gf = sigt(f0 + f1);                                     \
    const float gg = tanha(g0 + g1);                                    \
    const float cn = fmaf(gf, (C), gi * gg);                            \
    const float tc = tanha(cn);                                         \
    float o0 = z4.w, o1 = 0.f;                                          \
    CHAIN4(o0, h0, wo, 0)  CHAIN4(o0, h1, wo, 4)                        \
    CHAIN4(o0, h2, wo, 8)  CHAIN4(o0, h3, wo,12)                        \
    CHAIN4(o1, h4, wo,16)  CHAIN4(o1, h5, wo,20)                        \
    CHAIN4(o1, h6, wo,24)  CHAIN4(o1, h7, wo,28)                        \
    const float go = sigt(o0 + o1);                                     \
    const float hn = go * tc;                                           \
    const bool  m  = (tok != 0);                                        \
    C = m ? cn : (C);                                                   \
    H = m ? hn : (H);                                                   \
    sts32(HA, H);                                                       \
    OP[(size_t)(tt) * HIDD] = H;                                        \
}

__global__ __launch_bounds__(128) void rec_kernel(
    const int*   __restrict__ tokens,
    const float* __restrict__ Wr,
    float*       __restrict__ out)
{
    __shared__ float hs[4][2][HIDD];

    const int w = threadIdx.x >> 5;
    const int j = threadIdx.x & 31;
    const int b0 = (blockIdx.x * 4 + w) * 2;     // this warp's two sequences
    const int b1 = b0 + 1;

    float wi[HIDD], wf[HIDD], wg[HIDD], wo[HIDD];   // shared by both seqs
    #pragma unroll
    for (int k = 0; k < HIDD; k++){
        wi[k] = Wr[k*GATE + j];
        wf[k] = Wr[k*GATE + j + 32];
        wg[k] = Wr[k*GATE + j + 64];
        wo[k] = Wr[k*GATE + j + 96];
    }

    const u32 hb0 = smem_u32(hs[w][0]);
    const u32 hb1 = smem_u32(hs[w][1]);
    const u32 ha0 = hb0 + (u32)j * 4u;
    const u32 ha1 = hb1 + (u32)j * 4u;

    const float4* __restrict__ zp0 = g_zx + (size_t)b0 * SEQ * HIDD + j;
    const float4* __restrict__ zp1 = g_zx + (size_t)b1 * SEQ * HIDD + j;
    const int*    __restrict__ tp0 = tokens + b0 * SEQ;
    const int*    __restrict__ tp1 = tokens + b1 * SEQ;
    float* op0 = out + (size_t)b0 * SEQ * HIDD + j;
    float* op1 = out + (size_t)b1 * SEQ * HIDD + j;

    // named ring slots, prefetch distance 2 (slot = t parity)
    float4 zA0 = zp0[0*HIDD], zB0 = zp0[1*HIDD];
    float4 zA1 = zp1[0*HIDD], zB1 = zp1[1*HIDD];
    int    tA0 = tp0[0],      tB0 = tp0[1];
    int    tA1 = tp1[0],      tB1 = tp1[1];

    sts32(ha0, 0.0f);
    sts32(ha1, 0.0f);
    float h0_ = 0.0f, c0_ = 0.0f, h1_ = 0.0f, c1_ = 0.0f;

    for (int t = 0; t < SEQ; t += 2){
        LSTM_BODY(hb0, ha0, zp0, tp0, op0, zA0, tA0, h0_, c0_, t)
        LSTM_BODY(hb1, ha1, zp1, tp1, op1, zA1, tA1, h1_, c1_, t)
        LSTM_BODY(hb0, ha0, zp0, tp0, op0, zB0, tB0, h0_, c0_, t + 1)
        LSTM_BODY(hb1, ha1, zp1, tp1, op1, zB1, tB1, h1_, c1_, t + 1)
    }
}

extern "C" void kernel_launch(void* const* d_in, const int* in_sizes, int n_in,
                              void* d_out, int out_size)
{
    (void)in_sizes; (void)n_in; (void)out_size;
    const int*   tokens = (const int*)  d_in[0];
    const float* emb    = (const float*)d_in[1];
    const float* Wk     = (const float*)d_in[2];
    const float* Wr     = (const float*)d_in[3];
    const float* bias   = (const float*)d_in[4];
    float* out = (float*)d_out;

    proj_kernel<<<BATCH, 256>>>(tokens, emb, Wk, bias);
    rec_kernel<<<BATCH / 8, 128>>>(tokens, Wr, out);
}

// round 14
// speedup vs baseline: 2.8910x; 2.8910x over previous
#include <cuda_runtime.h>

#define BATCH 256
#define SEQ   2048
#define EMBD  16
#define HIDD  32
#define GATE  128
#define VOCAB 5000

typedef unsigned int u32;

// Vocab-indexed input projection table: vp[v][j] = (i,f,g,o) pre-activations
// for token v, hid j. 5000*32*16B = 2.56 MB -> L2-resident.
__device__ float4 g_vp[(size_t)VOCAB * HIDD];

__device__ __forceinline__ float tanha(float x){
    float y; asm("tanh.approx.f32 %0, %1;" : "=f"(y) : "f"(x)); return y;
}
// sigmoid(z) = 0.5 + 0.5*tanh(z/2)
__device__ __forceinline__ float sigt(float z){
    return fmaf(0.5f, tanha(0.5f * z), 0.5f);
}
__device__ __forceinline__ u32 smem_u32(const void* p){
    u32 a;
    asm("{ .reg .u64 t; cvta.to.shared.u64 t, %1; cvt.u32.u64 %0, t; }"
        : "=r"(a) : "l"(p));
    return a;
}
__device__ __forceinline__ void sts32(u32 addr, float v){
    asm volatile("st.shared.f32 [%0], %1;" :: "r"(addr), "f"(v) : "memory");
}
__device__ __forceinline__ float4 lds128(u32 addr){
    float4 v;
    asm volatile("ld.shared.v4.f32 {%0,%1,%2,%3}, [%4];"
        : "=f"(v.x), "=f"(v.y), "=f"(v.z), "=f"(v.w) : "r"(addr));
    return v;
}

// ─────────────── Phase 0: vp[v] = emb[v]@Wk + b  (5000 rows, ~5us) ──────────
__global__ __launch_bounds__(128) void vproj_kernel(
    const float* __restrict__ emb,
    const float* __restrict__ Wk,
    const float* __restrict__ bias)
{
    const int j   = threadIdx.x & 31;
    const int wid = (blockIdx.x << 2) + (threadIdx.x >> 5);
    const int nw  = gridDim.x << 2;

    float wk0[EMBD], wk1[EMBD], wk2[EMBD], wk3[EMBD];
    #pragma unroll
    for (int e = 0; e < EMBD; e++){
        wk0[e] = Wk[e*GATE + j];
        wk1[e] = Wk[e*GATE + j + 32];
        wk2[e] = Wk[e*GATE + j + 64];
        wk3[e] = Wk[e*GATE + j + 96];
    }
    const float b0 = bias[j], b1 = bias[j+32], b2 = bias[j+64], b3 = bias[j+96];

    for (int v = wid; v < VOCAB; v += nw){
        const float* x = emb + v * EMBD;
        float zi = b0, zf = b1, zg = b2, zo = b3;
        #pragma unroll
        for (int e = 0; e < EMBD; e++){
            const float xe = x[e];           // warp-broadcast, L1/L2-hot
            zi = fmaf(xe, wk0[e], zi);
            zf = fmaf(xe, wk1[e], zf);
            zg = fmaf(xe, wk2[e], zg);
            zo = fmaf(xe, wk3[e], zo);
        }
        g_vp[(size_t)v * HIDD + j] = make_float4(zi, zf, zg, zo);
    }
}

// ─────────────── Phase 2: R11 record structure + direct vp gather ───────────
// One warp per sequence; lane j owns hid j + gate cols (j,j+32,j+64,j+96).
// Spill-proof named scalar rings, hand-unrolled 4x, barrier-free private smem
// h handoff (volatile STS->LDS same-warp order). zx comes straight from the
// L2-resident vp table: token ring distance 4 (tA..tD), z ring distance 2
// (zA,zB; slot t&1) — the indirect load's token was fetched 2 bodies (~970cy)
// earlier, the z L2 hit (~234cy) is covered by the 2-body window.
#define CHAIN4(acc, hh, ww, base)                       \
    acc = fmaf((hh).x, ww[(base)  ], acc);              \
    acc = fmaf((hh).y, ww[(base)+1], acc);              \
    acc = fmaf((hh).z, ww[(base)+2], acc);              \
    acc = fmaf((hh).w, ww[(base)+3], acc);

#define LSTM_BODY(Z, TKC, TKZ, tt)                                      \
{                                                                       \
    const float4 z4  = Z;                                               \
    const int    tok = TKC;                                             \
    TKC = tptr[min((tt) + 4, SEQ - 1)];   /* token for step tt+4 */     \
    Z   = vpj[(size_t)(TKZ) * HIDD];      /* zx for step tt+2 */        \
    const float4 h0 = lds128(hbase +   0u);                             \
    const float4 h1 = lds128(hbase +  16u);                             \
    const float4 h2 = lds128(hbase +  32u);                             \
    const float4 h3 = lds128(hbase +  48u);                             \
    const float4 h4 = lds128(hbase +  64u);                             \
    const float4 h5 = lds128(hbase +  80u);                             \
    const float4 h6 = lds128(hbase +  96u);                             \
    const float4 h7 = lds128(hbase + 112u);                             \
    float i0 = z4.x, f0 = z4.y, g0 = z4.z;                              \
    float i1 = 0.f,  f1 = 0.f,  g1 = 0.f;                               \
    CHAIN4(i0, h0, wi, 0)  CHAIN4(f0, h0, wf, 0)  CHAIN4(g0, h0, wg, 0) \
    CHAIN4(i0, h1, wi, 4)  CHAIN4(f0, h1, wf, 4)  CHAIN4(g0, h1, wg, 4) \
    CHAIN4(i0, h2, wi, 8)  CHAIN4(f0, h2, wf, 8)  CHAIN4(g0, h2, wg, 8) \
    CHAIN4(i0, h3, wi,12)  CHAIN4(f0, h3, wf,12)  CHAIN4(g0, h3, wg,12) \
    CHAIN4(i1, h4, wi,16)  CHAIN4(f1, h4, wf,16)  CHAIN4(g1, h4, wg,16) \
    CHAIN4(i1, h5, wi,20)  CHAIN4(f1, h5, wf,20)  CHAIN4(g1, h5, wg,20) \
    CHAIN4(i1, h6, wi,24)  CHAIN4(f1, h6, wf,24)  CHAIN4(g1, h6, wg,24) \
    CHAIN4(i1, h7, wi,28)  CHAIN4(f1, h7, wf,28)  CHAIN4(g1, h7, wg,28) \
    const float gi = sigt(i0 + i1);                                     \
    const float gf = sigt(f0 + f1);                                     \
    const float gg = tanha(g0 + g1);                                    \
    const float cn = fmaf(gf, c, gi * gg);                              \
    const float tc = tanha(cn);                                         \
    float o0 = z4.w, o1 = 0.f;                                          \
    CHAIN4(o0, h0, wo, 0)  CHAIN4(o0, h1, wo, 4)                        \
    CHAIN4(o0, h2, wo, 8)  CHAIN4(o0, h3, wo,12)                        \
    CHAIN4(o1, h4, wo,16)  CHAIN4(o1, h5, wo,20)                        \
    CHAIN4(o1, h6, wo,24)  CHAIN4(o1, h7, wo,28)                        \
    const float go = sigt(o0 + o1);                                     \
    const float hn = go * tc;                                           \
    const bool  m  = (tok != 0);                                        \
    c = m ? cn : c;                                                     \
    h = m ? hn : h;                                                     \
    sts32(haddr, h);                                                    \
    optr[(size_t)(tt) * HIDD] = h;                                      \
}

__global__ __launch_bounds__(128) void rec_kernel(
    const int*   __restrict__ tokens,
    const float* __restrict__ Wr,
    float*       __restrict__ out)
{
    __shared__ float hs[4][HIDD];

    const int w = threadIdx.x >> 5;
    const int j = threadIdx.x & 31;
    const int b = blockIdx.x * 4 + w;

    float wi[HIDD], wf[HIDD], wg[HIDD], wo[HIDD];   // constant indices only
    #pragma unroll
    for (int k = 0; k < HIDD; k++){
        wi[k] = Wr[k*GATE + j];
        wf[k] = Wr[k*GATE + j + 32];
        wg[k] = Wr[k*GATE + j + 64];
        wo[k] = Wr[k*GATE + j + 96];
    }

    const u32 hbase = smem_u32(hs[w]);
    const u32 haddr = hbase + (u32)j * 4u;

    const float4* __restrict__ vpj  = g_vp + j;     // vpj[tok*HIDD]
    const int*    __restrict__ tptr = tokens + b * SEQ;
    float* optr = out + (size_t)b * SEQ * HIDD + j;

    // token ring distance 4; z ring distance 2 (slot = t parity)
    int tA = tptr[0], tB = tptr[1], tC = tptr[2], tD = tptr[3];
    float4 zA = vpj[(size_t)tA * HIDD];   // zx(0)
    float4 zB = vpj[(size_t)tB * HIDD];   // zx(1)

    sts32(haddr, 0.0f);
    float h = 0.0f, c = 0.0f;

    for (int t = 0; t < SEQ; t += 4){
        LSTM_BODY(zA, tA, tC, t + 0)   // consumes zx(t),   tok(t);   loads zx(t+2) via tC
        LSTM_BODY(zB, tB, tD, t + 1)   // consumes zx(t+1), tok(t+1); loads zx(t+3) via tD
        LSTM_BODY(zA, tC, tA, t + 2)   // tA now holds tok(t+4) (refilled at body t)
        LSTM_BODY(zB, tD, tB, t + 3)
    }
}

extern "C" void kernel_launch(void* const* d_in, const int* in_sizes, int n_in,
                              void* d_out, int out_size)
{
    (void)in_sizes; (void)n_in; (void)out_size;
    const int*   tokens = (const int*)  d_in[0];
    const float* emb    = (const float*)d_in[1];
    const float* Wk     = (const float*)d_in[2];
    const float* Wr     = (const float*)d_in[3];
    const float* bias   = (const float*)d_in[4];
    float* out = (float*)d_out;

    vproj_kernel<<<40, 128>>>(emb, Wk, bias);
    rec_kernel<<<BATCH / 4, 128>>>(tokens, Wr, out);
}